// round 1
// baseline (speedup 1.0000x reference)
#include <cuda_runtime.h>
#include <math_constants.h>

#define NB      256
#define LH      150
#define LQ      10
#define KITER   40
#define HH      64
#define WWID    64
#define HW      4096
#define VW      66            // 64 + 2 halo
#define VSZ     (VW*VW)       // 4356
#define QST     11            // q0 channel stride (conflict-free: gcd(11,32)=1)
#define NTHREADS 512

// smem float layout sizes
#define OFF_Q0    0
#define OFF_VA    (HW*QST)            // 45056
#define OFF_VB    (OFF_VA + VSZ)      // 49412
#define OFF_SW    (OFF_VB + VSZ)      // 53768  (iteration weights w, 90)
#define OFF_SWQ   (OFF_SW + 90)       // 53858  (Wq, 90)
#define OFF_WEFF  (OFF_SWQ + 90)      // 53948  (18)
#define OFF_BEFF  (OFF_WEFF + 18)     // 53966  (1)
#define OFF_RED   (OFF_BEFF + 1)      // 53967  (16)
#define SMEM_FLOATS 54016
#define SMEM_BYTES  (SMEM_FLOATS * 4)

__device__ __forceinline__ void load_vwin(const float* __restrict__ v, int y0, int tx,
                                          float vr[10][3]) {
#pragma unroll
    for (int jj = 0; jj < 10; jj++)
#pragma unroll
        for (int d = 0; d < 3; d++)
            vr[jj][d] = v[(y0 + jj) * VW + tx + d];
}

// One value-iteration step: q_c = q0_c + conv3x3(v, w_c); v' = max_c q_c.
// If LAST, also writes the full q tensor for this image to gmem.
template<bool LAST>
__device__ __forceinline__ void iter_body(
    const float* __restrict__ vcur, float* __restrict__ vnxt,
    const float* __restrict__ sq0, const float* __restrict__ sw,
    int y0, int tx, float* __restrict__ qout_b, float vmax[8])
{
    float vr[10][3];
    load_vwin(vcur, y0, tx, vr);
#pragma unroll
    for (int j = 0; j < 8; j++) vmax[j] = -CUDART_INF_F;
#pragma unroll
    for (int c = 0; c < LQ; c++) {
        const float w0 = sw[c*9+0], w1 = sw[c*9+1], w2 = sw[c*9+2];
        const float w3 = sw[c*9+3], w4 = sw[c*9+4], w5 = sw[c*9+5];
        const float w6 = sw[c*9+6], w7 = sw[c*9+7], w8 = sw[c*9+8];
#pragma unroll
        for (int j = 0; j < 8; j++) {
            float acc = sq0[((y0 + j) * WWID + tx) * QST + c];
            acc = fmaf(w0, vr[j  ][0], acc);
            acc = fmaf(w1, vr[j  ][1], acc);
            acc = fmaf(w2, vr[j  ][2], acc);
            acc = fmaf(w3, vr[j+1][0], acc);
            acc = fmaf(w4, vr[j+1][1], acc);
            acc = fmaf(w5, vr[j+1][2], acc);
            acc = fmaf(w6, vr[j+2][0], acc);
            acc = fmaf(w7, vr[j+2][1], acc);
            acc = fmaf(w8, vr[j+2][2], acc);
            vmax[j] = fmaxf(vmax[j], acc);
            if (LAST)
                qout_b[(size_t)c * HW + (y0 + j) * WWID + tx] = acc;
        }
    }
#pragma unroll
    for (int j = 0; j < 8; j++)
        vnxt[(y0 + j + 1) * VW + tx + 1] = vmax[j];
}

__global__ void __launch_bounds__(NTHREADS, 1)
vin_kernel(const float* __restrict__ X,  const float* __restrict__ Wh,
           const float* __restrict__ bh, const float* __restrict__ Wr,
           const float* __restrict__ Wq, const float* __restrict__ w,
           const float* __restrict__ Wc, const float* __restrict__ bc,
           float* __restrict__ out)
{
    extern __shared__ float smem[];
    float* sq0   = smem + OFF_Q0;
    float* vbufA = smem + OFF_VA;
    float* vbufB = smem + OFF_VB;
    float* sw    = smem + OFF_SW;
    float* sWq   = smem + OFF_SWQ;
    float* sweff = smem + OFF_WEFF;
    float* sbeff = smem + OFF_BEFF;
    float* sred  = smem + OFF_RED;

    const int tid = threadIdx.x;
    const int b   = blockIdx.x;
    const int tx  = tid & 63;
    const int ty  = tid >> 6;
    const int y0  = ty << 3;   // each thread owns 8 consecutive rows at column tx

    // ---- stage 1: zero v buffers (halo stays 0 forever), stage weights,
    //      partial reduction for effective 2->1 conv weight ----
    for (int i = tid; i < VSZ; i += NTHREADS) { vbufA[i] = 0.f; vbufB[i] = 0.f; }
    if (tid < 90) { sw[tid] = w[tid]; sWq[tid] = Wq[tid]; }
    {
        const int g = tid >> 5, k = tid & 31;   // 16 groups x 19 outputs
        if (k < 19) {
            float s = 0.f;
            for (int lh = g; lh < LH; lh += 16) {
                const float wr = Wr[lh];
                s += wr * ((k < 18) ? Wh[lh * 18 + k] : bh[lh]);
            }
            sq0[g * 19 + k] = s;   // sq0 used as scratch, overwritten later
        }
    }
    __syncthreads();

    // ---- stage 2: finalize Weff/beff; load X (2 channels) into v buffers ----
    if (tid < 19) {
        float s = 0.f;
#pragma unroll
        for (int g = 0; g < 16; g++) s += sq0[g * 19 + tid];
        if (tid < 18) sweff[tid] = s; else sbeff[0] = s;
    }
    const float* Xb = X + (size_t)b * 2 * HW;
    for (int i = tid; i < HW; i += NTHREADS) {
        const int yy = i >> 6, xx = i & 63;
        vbufA[(yy + 1) * VW + xx + 1] = Xb[i];
        vbufB[(yy + 1) * VW + xx + 1] = Xb[HW + i];
    }
    __syncthreads();

    // ---- stage 3: r = conv3x3(X, Weff) + beff  (into registers) ----
    float rreg[8];
    {
        float wef[18];
#pragma unroll
        for (int i = 0; i < 18; i++) wef[i] = sweff[i];
        const float be = sbeff[0];
        float va[10][3], vb[10][3];
        load_vwin(vbufA, y0, tx, va);
        load_vwin(vbufB, y0, tx, vb);
#pragma unroll
        for (int j = 0; j < 8; j++) {
            float acc = be;
#pragma unroll
            for (int t = 0; t < 9; t++) {
                const int ky = t / 3, kx = t % 3;
                acc = fmaf(wef[t],     va[j + ky][kx], acc);
                acc = fmaf(wef[9 + t], vb[j + ky][kx], acc);
            }
            rreg[j] = acc;
        }
    }
    __syncthreads();   // all X reads done before overwriting vbufA with r
#pragma unroll
    for (int j = 0; j < 8; j++) vbufA[(y0 + j + 1) * VW + tx + 1] = rreg[j];
    __syncthreads();

    // ---- stage 4: q0 = conv3x3(r, Wq) into smem (iteration-invariant),
    //      v0 = max_c q0 into vbufB ----
    {
        float vr[10][3];
        load_vwin(vbufA, y0, tx, vr);
        float vm[8];
#pragma unroll
        for (int j = 0; j < 8; j++) vm[j] = -CUDART_INF_F;
#pragma unroll
        for (int c = 0; c < LQ; c++) {
            const float w0 = sWq[c*9+0], w1 = sWq[c*9+1], w2 = sWq[c*9+2];
            const float w3 = sWq[c*9+3], w4 = sWq[c*9+4], w5 = sWq[c*9+5];
            const float w6 = sWq[c*9+6], w7 = sWq[c*9+7], w8 = sWq[c*9+8];
#pragma unroll
            for (int j = 0; j < 8; j++) {
                float acc = 0.f;
                acc = fmaf(w0, vr[j  ][0], acc);
                acc = fmaf(w1, vr[j  ][1], acc);
                acc = fmaf(w2, vr[j  ][2], acc);
                acc = fmaf(w3, vr[j+1][0], acc);
                acc = fmaf(w4, vr[j+1][1], acc);
                acc = fmaf(w5, vr[j+1][2], acc);
                acc = fmaf(w6, vr[j+2][0], acc);
                acc = fmaf(w7, vr[j+2][1], acc);
                acc = fmaf(w8, vr[j+2][2], acc);
                sq0[((y0 + j) * WWID + tx) * QST + c] = acc;
                vm[j] = fmaxf(vm[j], acc);
            }
        }
#pragma unroll
        for (int j = 0; j < 8; j++) vbufB[(y0 + j + 1) * VW + tx + 1] = vm[j];
    }

    // ---- stage 5: K=40 value-iteration steps, entirely in smem ----
    float* out_critic = out;
    float* out_q      = out + NB;
    float* qout_b     = out_q + (size_t)b * LQ * HW;
    float vmax[8];
    float* vcur = vbufB;
    float* vnxt = vbufA;   // r no longer needed; reuse (halo still 0)
#pragma unroll 1
    for (int k = 0; k < KITER - 1; k++) {
        __syncthreads();
        iter_body<false>(vcur, vnxt, sq0, sw, y0, tx, qout_b, vmax);
        float* t = vcur; vcur = vnxt; vnxt = t;
    }
    __syncthreads();
    iter_body<true>(vcur, vnxt, sq0, sw, y0, tx, qout_b, vmax);

    // ---- stage 6: critic = dot(v_final, Wc) + bc ----
    float part = 0.f;
#pragma unroll
    for (int j = 0; j < 8; j++)
        part = fmaf(vmax[j], Wc[(y0 + j) * WWID + tx], part);
#pragma unroll
    for (int off = 16; off > 0; off >>= 1)
        part += __shfl_down_sync(0xffffffffu, part, off);
    if ((tid & 31) == 0) sred[tid >> 5] = part;
    __syncthreads();
    if (tid < 32) {
        float s = (tid < 16) ? sred[tid] : 0.f;
#pragma unroll
        for (int off = 16; off > 0; off >>= 1)
            s += __shfl_down_sync(0xffffffffu, s, off);
        if (tid == 0) out_critic[b] = s + bc[0];
    }
}

extern "C" void kernel_launch(void* const* d_in, const int* in_sizes, int n_in,
                              void* d_out, int out_size) {
    const float* X  = (const float*)d_in[0];
    const float* Wh = (const float*)d_in[1];
    const float* bh = (const float*)d_in[2];
    const float* Wr = (const float*)d_in[3];
    const float* Wq = (const float*)d_in[4];
    const float* w  = (const float*)d_in[5];
    const float* Wc = (const float*)d_in[6];
    const float* bc = (const float*)d_in[7];
    float* out = (float*)d_out;

    cudaFuncSetAttribute(vin_kernel, cudaFuncAttributeMaxDynamicSharedMemorySize,
                         SMEM_BYTES);
    vin_kernel<<<NB, NTHREADS, SMEM_BYTES>>>(X, Wh, bh, Wr, Wq, w, Wc, bc, out);
}